// round 3
// baseline (speedup 1.0000x reference)
#include <cuda_runtime.h>
#include <cuda_bf16.h>
#include <cstdint>
#include <math.h>

typedef __nv_bfloat16 bf16;

#define BQ 4
#define TQ 2048
#define DQ 1024
#define BTQ 8192                 // B*T
#define NTT (TQ*TQ)              // 4194304
#define NBTD (BTQ*DQ)            // 8388608
#define PERB (TQ*DQ)             // 2097152

// ------------------------- scratch (device globals) -------------------------
__device__ bf16  g_ewh[NTT],  g_ewl[NTT];
__device__ bf16  g_xh[NBTD],  g_xl[NBTD];
__device__ bf16  g_wth[4][DQ*DQ], g_wtl[4][DQ*DQ];   // transposed weights hi/lo (q,k,v,o)
__device__ float g_qsig[NBTD], g_ek[NBTD], g_v[NBTD];
__device__ bf16  g_ekth[NBTD], g_ektl[NBTD], g_ekvth[NBTD], g_ekvtl[NBTD];
__device__ float g_num[NBTD], g_den[NBTD];
__device__ bf16  g_oph[NBTD], g_opl[NBTD];

// ------------------------------- helpers ------------------------------------
__device__ __forceinline__ uint32_t smem_u32(const void* p){
    uint32_t a;
    asm("{ .reg .u64 t; cvta.to.shared.u64 t, %1; cvt.u32.u64 %0, t; }" : "=r"(a) : "l"(p));
    return a;
}
__device__ __forceinline__ void ldsm4(uint32_t* r, uint32_t addr){
    asm volatile("ldmatrix.sync.aligned.m8n8.x4.shared.b16 {%0,%1,%2,%3}, [%4];"
        : "=r"(r[0]),"=r"(r[1]),"=r"(r[2]),"=r"(r[3]) : "r"(addr));
}
__device__ __forceinline__ void mma16816(float* d, const uint32_t* a, const uint32_t* b){
    asm volatile("mma.sync.aligned.m16n8k16.row.col.f32.bf16.bf16.f32 "
        "{%0,%1,%2,%3}, {%4,%5,%6,%7}, {%8,%9}, {%0,%1,%2,%3};"
        : "+f"(d[0]),"+f"(d[1]),"+f"(d[2]),"+f"(d[3])
        : "r"(a[0]),"r"(a[1]),"r"(a[2]),"r"(a[3]), "r"(b[0]),"r"(b[1]));
}
__device__ __forceinline__ void cp16(uint32_t saddr, const void* g){
    asm volatile("cp.async.cg.shared.global [%0], [%1], 16;" :: "r"(saddr), "l"(g));
}
__device__ __forceinline__ void fsplit(float f, bf16& h, bf16& l){
    h = __float2bfloat16(f);
    l = __float2bfloat16(f - __bfloat162float(h));
}
__device__ __forceinline__ uint32_t pk2(bf16 a, bf16 b){
    return (uint32_t)__bfloat16_as_ushort(a) | ((uint32_t)__bfloat16_as_ushort(b) << 16);
}

// --------------------------------- GEMM -------------------------------------
// C[m,n] (+bias, mode) = sum_k (Ah+Al)[m,k]*(Bh+Bl)[n,k], 3-pass bf16, f32 acc.
// A: [M,K] row-major, B: [N,K] row-major. BM=BN=128, BK=32, 256 thr, 3 stages.
struct GArgs {
    const bf16 *Ah, *Al, *Bh, *Bl;
    float* C;
    const float* bias;          // may be null
    int M, N, K, mode;          // mode: 0 none, 1 sigmoid, 2 exp
    long long sA, sB, sC;       // per-blockIdx.z element strides
};

#define PITCH_B     80                    // bytes per smem row (32 bf16 + pad)
#define TILE_BYTES  (128*PITCH_B)         // 10240
#define STAGE_BYTES (4*TILE_BYTES)        // 40960 (Ah,Al,Bh,Bl)
#define NSTAGE      3
#define GEMM_SMEM   (NSTAGE*STAGE_BYTES)  // 122880

__device__ __forceinline__ void issue_stage(
    uint32_t sb, const bf16* Ah, const bf16* Al, const bf16* Bh, const bf16* Bl,
    size_t ldk, int m0, int n0, int kt, int stage, int tid)
{
    uint32_t sbase = sb + stage*STAGE_BYTES;
    const bf16* bases[4] = {Ah, Al, Bh, Bl};
    int ro[4] = {m0, m0, n0, n0};
    #pragma unroll
    for (int i = 0; i < 8; i++){
        int tile = i >> 1;
        int c    = ((i & 1) << 8) + tid;      // 0..511 within tile
        int row  = c >> 2, ch = c & 3;
        uint32_t saddr = sbase + tile*TILE_BYTES + row*PITCH_B + ch*16;
        const bf16* g = bases[tile] + (size_t)(ro[tile] + row)*ldk
                      + (size_t)kt*32 + ch*8;
        cp16(saddr, g);
    }
    asm volatile("cp.async.commit_group;" ::: "memory");
}

__global__ void __launch_bounds__(256, 1)
gemm_k(GArgs g){
    extern __shared__ char smem[];
    uint32_t sb = smem_u32(smem);
    int tid = threadIdx.x, wid = tid >> 5, lane = tid & 31;
    int wm = wid & 1, wn = wid >> 1;           // 2 x 4 warp grid

    const bf16* Ah = g.Ah + (size_t)blockIdx.z * g.sA;
    const bf16* Al = g.Al + (size_t)blockIdx.z * g.sA;
    const bf16* Bh = g.Bh + (size_t)blockIdx.z * g.sB;
    const bf16* Bl = g.Bl + (size_t)blockIdx.z * g.sB;
    float*      C  = g.C  + (size_t)blockIdx.z * g.sC;
    int m0 = blockIdx.x * 128, n0 = blockIdx.y * 128;
    const size_t ldk = (size_t)g.K;
    const int KT = g.K >> 5;

    float acc[4][4][4];
    #pragma unroll
    for (int i = 0; i < 4; i++)
        #pragma unroll
        for (int f = 0; f < 4; f++)
            #pragma unroll
            for (int r = 0; r < 4; r++) acc[i][f][r] = 0.f;

    issue_stage(sb, Ah, Al, Bh, Bl, ldk, m0, n0, 0, 0, tid);
    issue_stage(sb, Ah, Al, Bh, Bl, ldk, m0, n0, 1, 1, tid);

    // ldmatrix lane addressing (fixed per thread)
    int a_row = wm*64 + (lane & 15);
    int a_koff = ((lane >> 4) & 1) * 8;
    int b_row = wn*32 + ((lane >> 4) & 1)*8 + (lane & 7);
    int b_koff = ((lane >> 3) & 1) * 8;

    for (int kt = 0; kt < KT; kt++){
        if (kt + 1 < KT) asm volatile("cp.async.wait_group 1;" ::: "memory");
        else             asm volatile("cp.async.wait_group 0;" ::: "memory");
        __syncthreads();
        if (kt + 2 < KT)
            issue_stage(sb, Ah, Al, Bh, Bl, ldk, m0, n0, kt+2, (kt+2)%NSTAGE, tid);

        uint32_t st = sb + (kt % NSTAGE)*STAGE_BYTES;
        #pragma unroll
        for (int j = 0; j < 2; j++){
            int ka = j*16 + a_koff;
            int kb = j*16 + b_koff;
            uint32_t ah[4][4], al[4][4], bh[2][4], bl[2][4];
            #pragma unroll
            for (int i = 0; i < 4; i++){
                uint32_t ra = st + (uint32_t)(a_row + i*16)*PITCH_B + ka*2;
                ldsm4(ah[i], ra);
                ldsm4(al[i], ra + TILE_BYTES);
            }
            #pragma unroll
            for (int q = 0; q < 2; q++){
                uint32_t rb = st + 2*TILE_BYTES + (uint32_t)(b_row + q*16)*PITCH_B + kb*2;
                ldsm4(bh[q], rb);
                ldsm4(bl[q], rb + TILE_BYTES);
            }
            #pragma unroll
            for (int i = 0; i < 4; i++)
                #pragma unroll
                for (int f = 0; f < 4; f++){
                    const uint32_t* Bhf = &bh[f >> 1][(f & 1)*2];
                    const uint32_t* Blf = &bl[f >> 1][(f & 1)*2];
                    mma16816(acc[i][f], ah[i], Bhf);
                    mma16816(acc[i][f], ah[i], Blf);
                    mma16816(acc[i][f], al[i], Bhf);
                }
        }
        __syncthreads();
    }

    // ------------------------------ epilogue --------------------------------
    int mb = m0 + wm*64 + (lane >> 2);
    int nb = n0 + wn*32 + (lane & 3)*2;
    #pragma unroll
    for (int i = 0; i < 4; i++){
        #pragma unroll
        for (int f = 0; f < 4; f++){
            int row = mb + i*16;
            int col = nb + f*8;
            float v0 = acc[i][f][0], v1 = acc[i][f][1];
            float v2 = acc[i][f][2], v3 = acc[i][f][3];
            if (g.bias){
                float b0 = __ldg(g.bias + col), b1 = __ldg(g.bias + col + 1);
                v0 += b0; v1 += b1; v2 += b0; v3 += b1;
            }
            if (g.mode == 1){
                v0 = 1.f/(1.f+expf(-v0)); v1 = 1.f/(1.f+expf(-v1));
                v2 = 1.f/(1.f+expf(-v2)); v3 = 1.f/(1.f+expf(-v3));
            } else if (g.mode == 2){
                v0 = expf(v0); v1 = expf(v1); v2 = expf(v2); v3 = expf(v3);
            }
            float2 o0; o0.x = v0; o0.y = v1;
            float2 o1; o1.x = v2; o1.y = v3;
            *(float2*)(C + (size_t)row * g.N + col)       = o0;
            *(float2*)(C + (size_t)(row + 8) * g.N + col) = o1;
        }
    }
}

// --------------------------- elementwise / prep ------------------------------
__global__ void k_split(const float* __restrict__ in, bf16* __restrict__ h, bf16* __restrict__ l){
    size_t i = (size_t)blockIdx.x * blockDim.x + threadIdx.x;
    float4 v = ((const float4*)in)[i];
    bf16 h0,h1,h2,h3,l0,l1,l2,l3;
    fsplit(v.x,h0,l0); fsplit(v.y,h1,l1); fsplit(v.z,h2,l2); fsplit(v.w,h3,l3);
    ((uint2*)h)[i] = make_uint2(pk2(h0,h1), pk2(h2,h3));
    ((uint2*)l)[i] = make_uint2(pk2(l0,l1), pk2(l2,l3));
}

__global__ void k_ew(const float* __restrict__ wb, bf16* __restrict__ h, bf16* __restrict__ l){
    size_t i = (size_t)blockIdx.x * blockDim.x + threadIdx.x;
    float4 v = ((const float4*)wb)[i];
    v.x = expf(v.x); v.y = expf(v.y); v.z = expf(v.z); v.w = expf(v.w);
    bf16 h0,h1,h2,h3,l0,l1,l2,l3;
    fsplit(v.x,h0,l0); fsplit(v.y,h1,l1); fsplit(v.z,h2,l2); fsplit(v.w,h3,l3);
    ((uint2*)h)[i] = make_uint2(pk2(h0,h1), pk2(h2,h3));
    ((uint2*)l)[i] = make_uint2(pk2(l0,l1), pk2(l2,l3));
}

__global__ void k_op(const float* __restrict__ q, const float* __restrict__ num,
                     const float* __restrict__ den, bf16* __restrict__ h, bf16* __restrict__ l){
    size_t i = (size_t)blockIdx.x * blockDim.x + threadIdx.x;
    float4 qv = ((const float4*)q)[i];
    float4 nv = ((const float4*)num)[i];
    float4 dv = ((const float4*)den)[i];
    float4 o;
    o.x = qv.x * nv.x / dv.x; o.y = qv.y * nv.y / dv.y;
    o.z = qv.z * nv.z / dv.z; o.w = qv.w * nv.w / dv.w;
    bf16 h0,h1,h2,h3,l0,l1,l2,l3;
    fsplit(o.x,h0,l0); fsplit(o.y,h1,l1); fsplit(o.z,h2,l2); fsplit(o.w,h3,l3);
    ((uint2*)h)[i] = make_uint2(pk2(h0,h1), pk2(h2,h3));
    ((uint2*)l)[i] = make_uint2(pk2(l0,l1), pk2(l2,l3));
}

// transpose W[rows,cols] -> T[cols,rows], split hi/lo
__global__ void k_tsplit(const float* __restrict__ W, bf16* __restrict__ Th,
                         bf16* __restrict__ Tl, int rows, int cols){
    __shared__ float t[32][33];
    int x  = blockIdx.x*32 + threadIdx.x;   // col
    int y0 = blockIdx.y*32;                 // row base
    for (int j = threadIdx.y; j < 32; j += 8)
        t[j][threadIdx.x] = W[(size_t)(y0 + j)*cols + x];
    __syncthreads();
    int x2  = y0 + threadIdx.x;             // out col (= orig row)
    int y20 = blockIdx.x*32;                // out row base (= orig col)
    for (int j = threadIdx.y; j < 32; j += 8){
        size_t o = (size_t)(y20 + j)*rows + x2;
        bf16 h, l; fsplit(t[threadIdx.x][j], h, l);
        Th[o] = h; Tl[o] = l;
    }
}

// per-batch: ekt[d][s]=ek[s][d], ekvt[d][s]=ek[s][d]*v[s][d], split hi/lo
__global__ void k_prep(const float* __restrict__ ek, const float* __restrict__ v,
                       bf16* __restrict__ kh, bf16* __restrict__ kl,
                       bf16* __restrict__ kvh, bf16* __restrict__ kvl){
    __shared__ float t1[32][33], t2[32][33];
    size_t base = (size_t)blockIdx.z * PERB;
    int x  = blockIdx.x*32 + threadIdx.x;   // d
    int y0 = blockIdx.y*32;                 // s base
    for (int j = threadIdx.y; j < 32; j += 8){
        float e  = ek[base + (size_t)(y0 + j)*DQ + x];
        float vv = v [base + (size_t)(y0 + j)*DQ + x];
        t1[j][threadIdx.x] = e;
        t2[j][threadIdx.x] = e * vv;
    }
    __syncthreads();
    int x2  = y0 + threadIdx.x;             // s (out col)
    int y20 = blockIdx.x*32;                // d base (out row)
    for (int j = threadIdx.y; j < 32; j += 8){
        size_t o = base + (size_t)(y20 + j)*TQ + x2;
        bf16 h, l;
        fsplit(t1[threadIdx.x][j], h, l); kh[o]  = h; kl[o]  = l;
        fsplit(t2[threadIdx.x][j], h, l); kvh[o] = h; kvl[o] = l;
    }
}

// --------------------------------- host -------------------------------------
extern "C" void kernel_launch(void* const* d_in, const int* in_sizes, int n_in,
                              void* d_out, int out_size){
    (void)in_sizes; (void)n_in; (void)out_size;
    const float* x  = (const float*)d_in[0];
    const float* W[4]    = {(const float*)d_in[1], (const float*)d_in[3],
                            (const float*)d_in[5], (const float*)d_in[7]};
    const float* bias[4] = {(const float*)d_in[2], (const float*)d_in[4],
                            (const float*)d_in[6], (const float*)d_in[8]};
    const float* wb = (const float*)d_in[9];
    float* out = (float*)d_out;

    void *ewh,*ewl,*xh,*xl,*wth,*wtl,*qsig,*ek,*v,*ekth,*ektl,*ekvth,*ekvtl,*num,*den,*oph,*opl;
    cudaGetSymbolAddress(&ewh, g_ewh);   cudaGetSymbolAddress(&ewl, g_ewl);
    cudaGetSymbolAddress(&xh, g_xh);     cudaGetSymbolAddress(&xl, g_xl);
    cudaGetSymbolAddress(&wth, g_wth);   cudaGetSymbolAddress(&wtl, g_wtl);
    cudaGetSymbolAddress(&qsig, g_qsig); cudaGetSymbolAddress(&ek, g_ek);
    cudaGetSymbolAddress(&v, g_v);
    cudaGetSymbolAddress(&ekth, g_ekth); cudaGetSymbolAddress(&ektl, g_ektl);
    cudaGetSymbolAddress(&ekvth, g_ekvth); cudaGetSymbolAddress(&ekvtl, g_ekvtl);
    cudaGetSymbolAddress(&num, g_num);   cudaGetSymbolAddress(&den, g_den);
    cudaGetSymbolAddress(&oph, g_oph);   cudaGetSymbolAddress(&opl, g_opl);

    cudaFuncSetAttribute(gemm_k, cudaFuncAttributeMaxDynamicSharedMemorySize, GEMM_SMEM);

    dim3 tb(32, 8);
    for (int i = 0; i < 4; i++)
        k_tsplit<<<dim3(32, 32), tb>>>(W[i], (bf16*)wth + (size_t)i*DQ*DQ,
                                       (bf16*)wtl + (size_t)i*DQ*DQ, DQ, DQ);
    k_split<<<NBTD/1024, 256>>>(x, (bf16*)xh, (bf16*)xl);
    k_ew<<<NTT/1024, 256>>>(wb, (bf16*)ewh, (bf16*)ewl);

    // projections: C = epi(X @ W + b)
    GArgs a{};
    a.Ah = (bf16*)xh; a.Al = (bf16*)xl;
    a.M = BTQ; a.N = DQ; a.K = DQ; a.sA = 0; a.sB = 0; a.sC = 0;

    a.Bh = (bf16*)wth + 0*DQ*DQ; a.Bl = (bf16*)wtl + 0*DQ*DQ;
    a.C = (float*)qsig; a.bias = bias[0]; a.mode = 1;          // sigmoid(Q)
    gemm_k<<<dim3(BTQ/128, DQ/128, 1), 256, GEMM_SMEM>>>(a);

    a.Bh = (bf16*)wth + 1*DQ*DQ; a.Bl = (bf16*)wtl + 1*DQ*DQ;
    a.C = (float*)ek; a.bias = bias[1]; a.mode = 2;            // exp(K)
    gemm_k<<<dim3(BTQ/128, DQ/128, 1), 256, GEMM_SMEM>>>(a);

    a.Bh = (bf16*)wth + 2*DQ*DQ; a.Bl = (bf16*)wtl + 2*DQ*DQ;
    a.C = (float*)v; a.bias = bias[2]; a.mode = 0;             // V
    gemm_k<<<dim3(BTQ/128, DQ/128, 1), 256, GEMM_SMEM>>>(a);

    k_prep<<<dim3(DQ/32, TQ/32, BQ), tb>>>((float*)ek, (float*)v,
        (bf16*)ekth, (bf16*)ektl, (bf16*)ekvth, (bf16*)ekvtl);

    // mix: num/den = ew @ (ekv|ek), batched over z
    GArgs m{};
    m.Ah = (bf16*)ewh; m.Al = (bf16*)ewl;
    m.M = TQ; m.N = DQ; m.K = TQ; m.sA = 0; m.sB = PERB; m.sC = PERB;
    m.bias = nullptr; m.mode = 0;
    m.Bh = (bf16*)ekvth; m.Bl = (bf16*)ekvtl; m.C = (float*)num;
    gemm_k<<<dim3(TQ/128, DQ/128, BQ), 256, GEMM_SMEM>>>(m);
    m.Bh = (bf16*)ekth;  m.Bl = (bf16*)ektl;  m.C = (float*)den;
    gemm_k<<<dim3(TQ/128, DQ/128, BQ), 256, GEMM_SMEM>>>(m);

    k_op<<<NBTD/1024, 256>>>((float*)qsig, (float*)num, (float*)den,
                             (bf16*)oph, (bf16*)opl);

    // out = OP @ Wo + bo
    GArgs f{};
    f.Ah = (bf16*)oph; f.Al = (bf16*)opl;
    f.Bh = (bf16*)wth + 3*DQ*DQ; f.Bl = (bf16*)wtl + 3*DQ*DQ;
    f.C = out; f.bias = bias[3]; f.mode = 0;
    f.M = BTQ; f.N = DQ; f.K = DQ; f.sA = 0; f.sB = 0; f.sC = 0;
    gemm_k<<<dim3(BTQ/128, DQ/128, 1), 256, GEMM_SMEM>>>(f);
}

// round 4
// speedup vs baseline: 1.1149x; 1.1149x over previous
#include <cuda_runtime.h>
#include <cuda_bf16.h>
#include <cstdint>
#include <math.h>

typedef __nv_bfloat16 bf16;

#define BQ 4
#define TQ 2048
#define DQ 1024
#define BTQ 8192                 // B*T
#define NTT (TQ*TQ)              // 4194304
#define NBTD (BTQ*DQ)            // 8388608
#define PERB (TQ*DQ)             // 2097152

// ------------------------- scratch (device globals) -------------------------
__device__ bf16  g_ewh[NTT],  g_ewl[NTT];
__device__ bf16  g_xh[NBTD],  g_xl[NBTD];
__device__ bf16  g_wth[4][DQ*DQ], g_wtl[4][DQ*DQ];   // transposed weights hi/lo (q,k,v,o)
__device__ float g_qsig[NBTD], g_ek[NBTD], g_v[NBTD];
__device__ bf16  g_ekth[NBTD], g_ektl[NBTD], g_ekvth[NBTD], g_ekvtl[NBTD];
__device__ float g_num[NBTD], g_den[NBTD];
__device__ bf16  g_oph[NBTD], g_opl[NBTD];

// ------------------------------- helpers ------------------------------------
__device__ __forceinline__ uint32_t smem_u32(const void* p){
    uint32_t a;
    asm("{ .reg .u64 t; cvta.to.shared.u64 t, %1; cvt.u32.u64 %0, t; }" : "=r"(a) : "l"(p));
    return a;
}
__device__ __forceinline__ void ldsm4(uint32_t* r, uint32_t addr){
    asm volatile("ldmatrix.sync.aligned.m8n8.x4.shared.b16 {%0,%1,%2,%3}, [%4];"
        : "=r"(r[0]),"=r"(r[1]),"=r"(r[2]),"=r"(r[3]) : "r"(addr));
}
__device__ __forceinline__ void mma16816(float* d, const uint32_t* a, const uint32_t* b){
    asm volatile("mma.sync.aligned.m16n8k16.row.col.f32.bf16.bf16.f32 "
        "{%0,%1,%2,%3}, {%4,%5,%6,%7}, {%8,%9}, {%0,%1,%2,%3};"
        : "+f"(d[0]),"+f"(d[1]),"+f"(d[2]),"+f"(d[3])
        : "r"(a[0]),"r"(a[1]),"r"(a[2]),"r"(a[3]), "r"(b[0]),"r"(b[1]));
}
__device__ __forceinline__ void cp16(uint32_t saddr, const void* g){
    asm volatile("cp.async.cg.shared.global [%0], [%1], 16;" :: "r"(saddr), "l"(g));
}
__device__ __forceinline__ void fsplit(float f, bf16& h, bf16& l){
    h = __float2bfloat16(f);
    l = __float2bfloat16(f - __bfloat162float(h));
}
__device__ __forceinline__ uint32_t pk2(bf16 a, bf16 b){
    return (uint32_t)__bfloat16_as_ushort(a) | ((uint32_t)__bfloat16_as_ushort(b) << 16);
}

// --------------------------------- GEMM -------------------------------------
// Per blockIdx.z: C_z[m,n] (+bias_z, mode_z) = sum_k (Ah+Al)[m,k]*(Bh_z+Bl_z)[n,k]
// 3-pass bf16 hi/lo, f32 acc. A:[M,K] rm, B:[N,K] rm. BM=BN=128, BK=32, 256 thr.
#define MAXZ 8
struct GArgs {
    const bf16 *Ah, *Al;
    const bf16 *Bh[MAXZ], *Bl[MAXZ];
    float* C[MAXZ];
    const float* bias[MAXZ];    // may be null
    int mode[MAXZ];             // 0 none, 1 sigmoid, 2 exp
    int M, N, K;
};

#define PITCH_B     80                    // bytes per smem row (32 bf16 + pad)
#define TILE_BYTES  (128*PITCH_B)         // 10240
#define STAGE_BYTES (4*TILE_BYTES)        // 40960 (Ah,Al,Bh,Bl)
#define NSTAGE      4
#define GEMM_SMEM   (NSTAGE*STAGE_BYTES)  // 163840

__device__ __forceinline__ void issue_stage(
    uint32_t sb, const bf16* Ah, const bf16* Al, const bf16* Bh, const bf16* Bl,
    size_t ldk, int m0, int n0, int kt, int stage, int tid)
{
    uint32_t sbase = sb + stage*STAGE_BYTES;
    const bf16* bases[4] = {Ah, Al, Bh, Bl};
    int ro[4] = {m0, m0, n0, n0};
    #pragma unroll
    for (int i = 0; i < 8; i++){
        int tile = i >> 1;
        int c    = ((i & 1) << 8) + tid;      // 0..511 within tile
        int row  = c >> 2, ch = c & 3;
        uint32_t saddr = sbase + tile*TILE_BYTES + row*PITCH_B + ch*16;
        const bf16* g = bases[tile] + (size_t)(ro[tile] + row)*ldk
                      + (size_t)kt*32 + ch*8;
        cp16(saddr, g);
    }
    asm volatile("cp.async.commit_group;" ::: "memory");
}

__global__ void __launch_bounds__(256, 1)
gemm_k(GArgs g){
    extern __shared__ char smem[];
    uint32_t sb = smem_u32(smem);
    int tid = threadIdx.x, wid = tid >> 5, lane = tid & 31;
    int wm = wid & 1, wn = wid >> 1;           // 2 x 4 warp grid
    int z = blockIdx.z;

    const bf16* Ah = g.Ah;
    const bf16* Al = g.Al;
    const bf16* Bh = g.Bh[z];
    const bf16* Bl = g.Bl[z];
    float*      C  = g.C[z];
    const float* bias = g.bias[z];
    int mode = g.mode[z];
    int m0 = blockIdx.x * 128, n0 = blockIdx.y * 128;
    const size_t ldk = (size_t)g.K;
    const int KT = g.K >> 5;

    float acc[4][4][4];
    #pragma unroll
    for (int i = 0; i < 4; i++)
        #pragma unroll
        for (int f = 0; f < 4; f++)
            #pragma unroll
            for (int r = 0; r < 4; r++) acc[i][f][r] = 0.f;

    issue_stage(sb, Ah, Al, Bh, Bl, ldk, m0, n0, 0, 0, tid);
    issue_stage(sb, Ah, Al, Bh, Bl, ldk, m0, n0, 1, 1, tid);
    issue_stage(sb, Ah, Al, Bh, Bl, ldk, m0, n0, 2, 2, tid);

    // ldmatrix lane addressing (fixed per thread)
    int a_row = wm*64 + (lane & 15);
    int a_koff = ((lane >> 4) & 1) * 8;
    int b_row = wn*32 + ((lane >> 4) & 1)*8 + (lane & 7);
    int b_koff = ((lane >> 3) & 1) * 8;

    for (int kt = 0; kt < KT; kt++){
        int ahead = KT - 1 - kt; if (ahead > 2) ahead = 2;
        if (ahead == 2)      asm volatile("cp.async.wait_group 2;" ::: "memory");
        else if (ahead == 1) asm volatile("cp.async.wait_group 1;" ::: "memory");
        else                 asm volatile("cp.async.wait_group 0;" ::: "memory");
        __syncthreads();

        if (kt + 3 < KT)
            issue_stage(sb, Ah, Al, Bh, Bl, ldk, m0, n0, kt+3, (kt+3) & 3, tid);

        uint32_t st = sb + (kt & 3)*STAGE_BYTES;
        #pragma unroll
        for (int j = 0; j < 2; j++){
            int ka = j*16 + a_koff;
            int kb = j*16 + b_koff;
            uint32_t ah[4][4], al[4][4], bh[2][4], bl[2][4];
            #pragma unroll
            for (int i = 0; i < 4; i++){
                uint32_t ra = st + (uint32_t)(a_row + i*16)*PITCH_B + ka*2;
                ldsm4(ah[i], ra);
                ldsm4(al[i], ra + TILE_BYTES);
            }
            #pragma unroll
            for (int q = 0; q < 2; q++){
                uint32_t rb = st + 2*TILE_BYTES + (uint32_t)(b_row + q*16)*PITCH_B + kb*2;
                ldsm4(bh[q], rb);
                ldsm4(bl[q], rb + TILE_BYTES);
            }
            // pass-outermost: 16 independent acc tiles between reuses of any acc
            #pragma unroll
            for (int p = 0; p < 3; p++)
                #pragma unroll
                for (int i = 0; i < 4; i++)
                    #pragma unroll
                    for (int f = 0; f < 4; f++){
                        const uint32_t* af = (p == 2) ? al[i] : ah[i];
                        const uint32_t* bf_ = (p == 1) ? &bl[f >> 1][(f & 1)*2]
                                                       : &bh[f >> 1][(f & 1)*2];
                        mma16816(acc[i][f], af, bf_);
                    }
        }
    }

    // ------------------------------ epilogue --------------------------------
    int mb = m0 + wm*64 + (lane >> 2);
    int nb = n0 + wn*32 + (lane & 3)*2;
    #pragma unroll
    for (int i = 0; i < 4; i++){
        #pragma unroll
        for (int f = 0; f < 4; f++){
            int row = mb + i*16;
            int col = nb + f*8;
            float v0 = acc[i][f][0], v1 = acc[i][f][1];
            float v2 = acc[i][f][2], v3 = acc[i][f][3];
            if (bias){
                float b0 = __ldg(bias + col), b1 = __ldg(bias + col + 1);
                v0 += b0; v1 += b1; v2 += b0; v3 += b1;
            }
            if (mode == 1){
                v0 = 1.f/(1.f+expf(-v0)); v1 = 1.f/(1.f+expf(-v1));
                v2 = 1.f/(1.f+expf(-v2)); v3 = 1.f/(1.f+expf(-v3));
            } else if (mode == 2){
                v0 = expf(v0); v1 = expf(v1); v2 = expf(v2); v3 = expf(v3);
            }
            float2 o0; o0.x = v0; o0.y = v1;
            float2 o1; o1.x = v2; o1.y = v3;
            *(float2*)(C + (size_t)row * g.N + col)       = o0;
            *(float2*)(C + (size_t)(row + 8) * g.N + col) = o1;
        }
    }
}

// --------------------------- elementwise / prep ------------------------------
__global__ void k_split(const float* __restrict__ in, bf16* __restrict__ h, bf16* __restrict__ l){
    size_t i = (size_t)blockIdx.x * blockDim.x + threadIdx.x;
    float4 v = ((const float4*)in)[i];
    bf16 h0,h1,h2,h3,l0,l1,l2,l3;
    fsplit(v.x,h0,l0); fsplit(v.y,h1,l1); fsplit(v.z,h2,l2); fsplit(v.w,h3,l3);
    ((uint2*)h)[i] = make_uint2(pk2(h0,h1), pk2(h2,h3));
    ((uint2*)l)[i] = make_uint2(pk2(l0,l1), pk2(l2,l3));
}

__global__ void k_ew(const float* __restrict__ wb, bf16* __restrict__ h, bf16* __restrict__ l){
    size_t i = (size_t)blockIdx.x * blockDim.x + threadIdx.x;
    float4 v = ((const float4*)wb)[i];
    v.x = expf(v.x); v.y = expf(v.y); v.z = expf(v.z); v.w = expf(v.w);
    bf16 h0,h1,h2,h3,l0,l1,l2,l3;
    fsplit(v.x,h0,l0); fsplit(v.y,h1,l1); fsplit(v.z,h2,l2); fsplit(v.w,h3,l3);
    ((uint2*)h)[i] = make_uint2(pk2(h0,h1), pk2(h2,h3));
    ((uint2*)l)[i] = make_uint2(pk2(l0,l1), pk2(l2,l3));
}

__global__ void k_op(const float* __restrict__ q, const float* __restrict__ num,
                     const float* __restrict__ den, bf16* __restrict__ h, bf16* __restrict__ l){
    size_t i = (size_t)blockIdx.x * blockDim.x + threadIdx.x;
    float4 qv = ((const float4*)q)[i];
    float4 nv = ((const float4*)num)[i];
    float4 dv = ((const float4*)den)[i];
    float4 o;
    o.x = qv.x * nv.x / dv.x; o.y = qv.y * nv.y / dv.y;
    o.z = qv.z * nv.z / dv.z; o.w = qv.w * nv.w / dv.w;
    bf16 h0,h1,h2,h3,l0,l1,l2,l3;
    fsplit(o.x,h0,l0); fsplit(o.y,h1,l1); fsplit(o.z,h2,l2); fsplit(o.w,h3,l3);
    ((uint2*)h)[i] = make_uint2(pk2(h0,h1), pk2(h2,h3));
    ((uint2*)l)[i] = make_uint2(pk2(l0,l1), pk2(l2,l3));
}

// transpose all four weights W_z[DQ,DQ] -> T_z[DQ,DQ] (z = blockIdx.z), split hi/lo
__global__ void k_tsplit4(const float* __restrict__ W0, const float* __restrict__ W1,
                          const float* __restrict__ W2, const float* __restrict__ W3,
                          bf16* __restrict__ Th, bf16* __restrict__ Tl){
    __shared__ float t[32][33];
    int z = blockIdx.z;
    const float* W = (z == 0) ? W0 : (z == 1) ? W1 : (z == 2) ? W2 : W3;
    bf16* th = Th + (size_t)z*DQ*DQ;
    bf16* tl = Tl + (size_t)z*DQ*DQ;
    int x  = blockIdx.x*32 + threadIdx.x;   // col
    int y0 = blockIdx.y*32;                 // row base
    for (int j = threadIdx.y; j < 32; j += 8)
        t[j][threadIdx.x] = W[(size_t)(y0 + j)*DQ + x];
    __syncthreads();
    int x2  = y0 + threadIdx.x;             // out col (= orig row)
    int y20 = blockIdx.x*32;                // out row base (= orig col)
    for (int j = threadIdx.y; j < 32; j += 8){
        size_t o = (size_t)(y20 + j)*DQ + x2;
        bf16 h, l; fsplit(t[threadIdx.x][j], h, l);
        th[o] = h; tl[o] = l;
    }
}

// per-batch: ekt[d][s]=ek[s][d], ekvt[d][s]=ek[s][d]*v[s][d], split hi/lo
__global__ void k_prep(const float* __restrict__ ek, const float* __restrict__ v,
                       bf16* __restrict__ kh, bf16* __restrict__ kl,
                       bf16* __restrict__ kvh, bf16* __restrict__ kvl){
    __shared__ float t1[32][33], t2[32][33];
    size_t base = (size_t)blockIdx.z * PERB;
    int x  = blockIdx.x*32 + threadIdx.x;   // d
    int y0 = blockIdx.y*32;                 // s base
    for (int j = threadIdx.y; j < 32; j += 8){
        float e  = ek[base + (size_t)(y0 + j)*DQ + x];
        float vv = v [base + (size_t)(y0 + j)*DQ + x];
        t1[j][threadIdx.x] = e;
        t2[j][threadIdx.x] = e * vv;
    }
    __syncthreads();
    int x2  = y0 + threadIdx.x;             // s (out col)
    int y20 = blockIdx.x*32;                // d base (out row)
    for (int j = threadIdx.y; j < 32; j += 8){
        size_t o = base + (size_t)(y20 + j)*TQ + x2;
        bf16 h, l;
        fsplit(t1[threadIdx.x][j], h, l); kh[o]  = h; kl[o]  = l;
        fsplit(t2[threadIdx.x][j], h, l); kvh[o] = h; kvl[o] = l;
    }
}

// --------------------------------- host -------------------------------------
extern "C" void kernel_launch(void* const* d_in, const int* in_sizes, int n_in,
                              void* d_out, int out_size){
    (void)in_sizes; (void)n_in; (void)out_size;
    const float* x  = (const float*)d_in[0];
    const float* W[4]    = {(const float*)d_in[1], (const float*)d_in[3],
                            (const float*)d_in[5], (const float*)d_in[7]};
    const float* bias[4] = {(const float*)d_in[2], (const float*)d_in[4],
                            (const float*)d_in[6], (const float*)d_in[8]};
    const float* wb = (const float*)d_in[9];
    float* out = (float*)d_out;

    void *ewh,*ewl,*xh,*xl,*wth,*wtl,*qsig,*ek,*v,*ekth,*ektl,*ekvth,*ekvtl,*num,*den,*oph,*opl;
    cudaGetSymbolAddress(&ewh, g_ewh);   cudaGetSymbolAddress(&ewl, g_ewl);
    cudaGetSymbolAddress(&xh, g_xh);     cudaGetSymbolAddress(&xl, g_xl);
    cudaGetSymbolAddress(&wth, g_wth);   cudaGetSymbolAddress(&wtl, g_wtl);
    cudaGetSymbolAddress(&qsig, g_qsig); cudaGetSymbolAddress(&ek, g_ek);
    cudaGetSymbolAddress(&v, g_v);
    cudaGetSymbolAddress(&ekth, g_ekth); cudaGetSymbolAddress(&ektl, g_ektl);
    cudaGetSymbolAddress(&ekvth, g_ekvth); cudaGetSymbolAddress(&ekvtl, g_ekvtl);
    cudaGetSymbolAddress(&num, g_num);   cudaGetSymbolAddress(&den, g_den);
    cudaGetSymbolAddress(&oph, g_oph);   cudaGetSymbolAddress(&opl, g_opl);

    cudaFuncSetAttribute(gemm_k, cudaFuncAttributeMaxDynamicSharedMemorySize, GEMM_SMEM);

    dim3 tb(32, 8);
    k_tsplit4<<<dim3(32, 32, 4), tb>>>(W[0], W[1], W[2], W[3], (bf16*)wth, (bf16*)wtl);
    k_split<<<NBTD/1024, 256>>>(x, (bf16*)xh, (bf16*)xl);
    k_ew<<<NTT/1024, 256>>>(wb, (bf16*)ewh, (bf16*)ewl);

    // projections (one launch, z = q,k,v): C_z = epi_z(X @ W_z + b_z)
    {
        GArgs a{};
        a.Ah = (bf16*)xh; a.Al = (bf16*)xl;
        a.M = BTQ; a.N = DQ; a.K = DQ;
        float* Cs[3] = {(float*)qsig, (float*)ek, (float*)v};
        int modes[3] = {1, 2, 0};
        for (int z = 0; z < 3; z++){
            a.Bh[z] = (bf16*)wth + (size_t)z*DQ*DQ;
            a.Bl[z] = (bf16*)wtl + (size_t)z*DQ*DQ;
            a.C[z] = Cs[z]; a.bias[z] = bias[z]; a.mode[z] = modes[z];
        }
        gemm_k<<<dim3(BTQ/128, DQ/128, 3), 256, GEMM_SMEM>>>(a);
    }

    k_prep<<<dim3(DQ/32, TQ/32, BQ), tb>>>((float*)ek, (float*)v,
        (bf16*)ekth, (bf16*)ektl, (bf16*)ekvth, (bf16*)ekvtl);

    // mix (one launch, z = 4 batches x {num, den}): ew @ (ekv|ek)
    {
        GArgs m{};
        m.Ah = (bf16*)ewh; m.Al = (bf16*)ewl;
        m.M = TQ; m.N = DQ; m.K = TQ;
        for (int z = 0; z < 8; z++){
            int b = z & 3;
            if (z < 4){
                m.Bh[z] = (bf16*)ekvth + (size_t)b*PERB;
                m.Bl[z] = (bf16*)ekvtl + (size_t)b*PERB;
                m.C[z]  = (float*)num + (size_t)b*PERB;
            } else {
                m.Bh[z] = (bf16*)ekth + (size_t)b*PERB;
                m.Bl[z] = (bf16*)ektl + (size_t)b*PERB;
                m.C[z]  = (float*)den + (size_t)b*PERB;
            }
            m.bias[z] = nullptr; m.mode[z] = 0;
        }
        gemm_k<<<dim3(TQ/128, DQ/128, 8), 256, GEMM_SMEM>>>(m);
    }

    k_op<<<NBTD/1024, 256>>>((float*)qsig, (float*)num, (float*)den,
                             (bf16*)oph, (bf16*)opl);

    // out = OP @ Wo + bo
    {
        GArgs f{};
        f.Ah = (bf16*)oph; f.Al = (bf16*)opl;
        f.Bh[0] = (bf16*)wth + (size_t)3*DQ*DQ;
        f.Bl[0] = (bf16*)wtl + (size_t)3*DQ*DQ;
        f.C[0] = out; f.bias[0] = bias[3]; f.mode[0] = 0;
        f.M = BTQ; f.N = DQ; f.K = DQ;
        gemm_k<<<dim3(BTQ/128, DQ/128, 1), 256, GEMM_SMEM>>>(f);
    }
}

// round 6
// speedup vs baseline: 1.7364x; 1.5575x over previous
#include <cuda_runtime.h>
#include <cuda_bf16.h>
#include <cuda_fp16.h>
#include <cstdint>
#include <math.h>

typedef __nv_bfloat16 bf16;

#define BQ 4
#define TQ 2048
#define DQ 1024
#define BTQ 8192                 // B*T
#define NTT (TQ*TQ)              // 4194304
#define NBTD (BTQ*DQ)            // 8388608
#define PERB (TQ*DQ)             // 2097152

// ------------------------- scratch (device globals) -------------------------
__device__ __half g_ewh[NTT],  g_ewl[NTT];            // fp16 hi/lo of exp(wbias)
__device__ bf16   g_xh[NBTD],  g_xl[NBTD];
__device__ bf16   g_wth[4][DQ*DQ], g_wtl[4][DQ*DQ];   // transposed weights hi/lo
__device__ float  g_qsig[NBTD], g_ek[NBTD], g_v[NBTD];
__device__ __half g_ekt[NBTD], g_ekvt[NBTD];          // fp16 single (B of mix)
__device__ float  g_num[NBTD], g_den[NBTD];
__device__ bf16   g_oph[NBTD], g_opl[NBTD];

// ------------------------------- helpers ------------------------------------
__device__ __forceinline__ uint32_t smem_u32(const void* p){
    uint32_t a;
    asm("{ .reg .u64 t; cvta.to.shared.u64 t, %1; cvt.u32.u64 %0, t; }" : "=r"(a) : "l"(p));
    return a;
}
__device__ __forceinline__ void ldsm4(uint32_t* r, uint32_t addr){
    asm volatile("ldmatrix.sync.aligned.m8n8.x4.shared.b16 {%0,%1,%2,%3}, [%4];"
        : "=r"(r[0]),"=r"(r[1]),"=r"(r[2]),"=r"(r[3]) : "r"(addr));
}
__device__ __forceinline__ void mma_bf16(float* d, const uint32_t* a, const uint32_t* b){
    asm volatile("mma.sync.aligned.m16n8k16.row.col.f32.bf16.bf16.f32 "
        "{%0,%1,%2,%3}, {%4,%5,%6,%7}, {%8,%9}, {%0,%1,%2,%3};"
        : "+f"(d[0]),"+f"(d[1]),"+f"(d[2]),"+f"(d[3])
        : "r"(a[0]),"r"(a[1]),"r"(a[2]),"r"(a[3]), "r"(b[0]),"r"(b[1]));
}
__device__ __forceinline__ void mma_f16(float* d, const uint32_t* a, const uint32_t* b){
    asm volatile("mma.sync.aligned.m16n8k16.row.col.f32.f16.f16.f32 "
        "{%0,%1,%2,%3}, {%4,%5,%6,%7}, {%8,%9}, {%0,%1,%2,%3};"
        : "+f"(d[0]),"+f"(d[1]),"+f"(d[2]),"+f"(d[3])
        : "r"(a[0]),"r"(a[1]),"r"(a[2]),"r"(a[3]), "r"(b[0]),"r"(b[1]));
}
__device__ __forceinline__ void cp16(uint32_t saddr, const void* g){
    asm volatile("cp.async.cg.shared.global [%0], [%1], 16;" :: "r"(saddr), "l"(g));
}
__device__ __forceinline__ void fsplit(float f, bf16& h, bf16& l){
    h = __float2bfloat16(f);
    l = __float2bfloat16(f - __bfloat162float(h));
}
__device__ __forceinline__ void fsplit_h(float f, __half& h, __half& l){
    h = __float2half(f);
    l = __float2half(f - __half2float(h));
}
__device__ __forceinline__ uint32_t pk2(bf16 a, bf16 b){
    return (uint32_t)__bfloat16_as_ushort(a) | ((uint32_t)__bfloat16_as_ushort(b) << 16);
}
__device__ __forceinline__ uint32_t pk2h(__half a, __half b){
    return (uint32_t)__half_as_ushort(a) | ((uint32_t)__half_as_ushort(b) << 16);
}

// 128-row x 32-elem (64B) tile, XOR-swizzled: 16B-aligned, LDSM conflict-free
#define TILE_BYTES 8192
__device__ __forceinline__ uint32_t swz(uint32_t row, uint32_t chunk){
    return row*64u + (((chunk ^ (row >> 1)) & 3u) << 4);
}

// --------------------------------- GEMM -------------------------------------
// NPASS=3: bf16 hi/lo 3-pass  C = (Ah+Al)(Bh+Bl)^T ~ AhBh + AhBl + AlBh
// NPASS=2: fp16 A-split 2-pass C = (Ah+Al) B^T,  B single fp16
// A:[M,K] row-major, B:[N,K] row-major. BM=BN=128, BK=32, 256 thr.
#define MAXZ 8
struct GArgs {
    const void *Ah, *Al;
    const void *B0[MAXZ], *B1[MAXZ];   // B1 unused for NPASS=2
    float* C[MAXZ];
    const float* bias[MAXZ];           // may be null
    int mode[MAXZ];                    // 0 none, 1 sigmoid, 2 exp
    int M, N, K;
};

template<int NPASS>
__global__ void __launch_bounds__(256, 2)
gemm_k(GArgs g){
    constexpr int NT   = (NPASS == 3) ? 4 : 3;        // tiles per stage
    constexpr int NST  = (NPASS == 3) ? 3 : 4;        // stages
    constexpr int PF   = NST - 1;                     // prefetch distance
    constexpr int STAGE = NT * TILE_BYTES;
    extern __shared__ char smem[];
    uint32_t sb = smem_u32(smem);
    int tid = threadIdx.x, wid = tid >> 5, lane = tid & 31;
    int wm = wid & 1, wn = wid >> 1;                  // 2 x 4 warp grid
    int z = blockIdx.z;

    const char* bases[4];
    bases[0] = (const char*)g.Ah;
    bases[1] = (const char*)g.Al;
    bases[2] = (const char*)g.B0[z];
    bases[3] = (NPASS == 3) ? (const char*)g.B1[z] : (const char*)g.B0[z];
    float* C = g.C[z];
    const float* bias = g.bias[z];
    int mode = g.mode[z];
    int m0 = blockIdx.x * 128, n0 = blockIdx.y * 128;
    const size_t ldk = (size_t)g.K;
    const int KT = g.K >> 5;
    int ro[4] = {m0, m0, n0, n0};

    float acc[4][4][4];
    #pragma unroll
    for (int i = 0; i < 4; i++)
        #pragma unroll
        for (int f = 0; f < 4; f++)
            #pragma unroll
            for (int r = 0; r < 4; r++) acc[i][f][r] = 0.f;

    auto issue = [&](int kt, int stage){
        uint32_t sbase = sb + stage*STAGE;
        #pragma unroll
        for (int t = 0; t < NT; t++){
            #pragma unroll
            for (int hh = 0; hh < 2; hh++){
                int c = (hh << 8) + tid;              // 0..511 within tile
                uint32_t row = (uint32_t)(c >> 2), ch = (uint32_t)(c & 3);
                uint32_t saddr = sbase + t*TILE_BYTES + swz(row, ch);
                const char* gp = bases[t]
                    + (((size_t)ro[t] + row)*ldk + (size_t)kt*32 + ch*8)*2;
                cp16(saddr, gp);
            }
        }
        asm volatile("cp.async.commit_group;" ::: "memory");
    };

    #pragma unroll
    for (int s = 0; s < PF; s++) issue(s, s);

    // ldmatrix lane addressing (fixed per thread)
    uint32_t a_row = wm*64 + (lane & 15);
    uint32_t a_ch0 = (lane >> 4) & 1;                 // chunk low bit for A
    uint32_t b_row = wn*32 + ((lane >> 4) & 1)*8 + (lane & 7);
    uint32_t b_ch0 = (lane >> 3) & 1;                 // chunk low bit for B

    for (int kt = 0; kt < KT; kt++){
        int ahead = KT - 1 - kt; if (ahead > PF - 1) ahead = PF - 1;
        if (PF == 3 && ahead == 2)      asm volatile("cp.async.wait_group 2;" ::: "memory");
        else if (ahead == 1)            asm volatile("cp.async.wait_group 1;" ::: "memory");
        else                            asm volatile("cp.async.wait_group 0;" ::: "memory");
        __syncthreads();
        if (kt + PF < KT) issue(kt + PF, (kt + PF) % NST);

        uint32_t st = sb + (kt % NST)*STAGE;
        #pragma unroll
        for (uint32_t j = 0; j < 2; j++){
            uint32_t ca = j*2 + a_ch0;                // A chunk index 0..3
            uint32_t cb = j*2 + b_ch0;                // B chunk index 0..3
            uint32_t a[4][4], b[2][4];

            // pass 0: Ah x B(h)
            #pragma unroll
            for (uint32_t i = 0; i < 4; i++)
                ldsm4(a[i], st + swz(a_row + i*16, ca));
            #pragma unroll
            for (uint32_t q = 0; q < 2; q++)
                ldsm4(b[q], st + 2*TILE_BYTES + swz(b_row + q*16, cb));
            #pragma unroll
            for (int i = 0; i < 4; i++)
                #pragma unroll
                for (int f = 0; f < 4; f++){
                    if (NPASS == 3) mma_bf16(acc[i][f], a[i], &b[f>>1][(f&1)*2]);
                    else            mma_f16 (acc[i][f], a[i], &b[f>>1][(f&1)*2]);
                }

            if (NPASS == 3){
                // pass 1: Ah x Bl (a kept live)
                #pragma unroll
                for (uint32_t q = 0; q < 2; q++)
                    ldsm4(b[q], st + 3*TILE_BYTES + swz(b_row + q*16, cb));
                #pragma unroll
                for (int i = 0; i < 4; i++)
                    #pragma unroll
                    for (int f = 0; f < 4; f++)
                        mma_bf16(acc[i][f], a[i], &b[f>>1][(f&1)*2]);
                // pass 2: Al x Bh
                #pragma unroll
                for (uint32_t i = 0; i < 4; i++)
                    ldsm4(a[i], st + TILE_BYTES + swz(a_row + i*16, ca));
                #pragma unroll
                for (uint32_t q = 0; q < 2; q++)
                    ldsm4(b[q], st + 2*TILE_BYTES + swz(b_row + q*16, cb));
                #pragma unroll
                for (int i = 0; i < 4; i++)
                    #pragma unroll
                    for (int f = 0; f < 4; f++)
                        mma_bf16(acc[i][f], a[i], &b[f>>1][(f&1)*2]);
            } else {
                // pass 1: Al x B (b kept live)
                #pragma unroll
                for (uint32_t i = 0; i < 4; i++)
                    ldsm4(a[i], st + TILE_BYTES + swz(a_row + i*16, ca));
                #pragma unroll
                for (int i = 0; i < 4; i++)
                    #pragma unroll
                    for (int f = 0; f < 4; f++)
                        mma_f16(acc[i][f], a[i], &b[f>>1][(f&1)*2]);
            }
        }
    }

    // ------------------------------ epilogue --------------------------------
    int mb = m0 + wm*64 + (lane >> 2);
    int nb = n0 + wn*32 + (lane & 3)*2;
    #pragma unroll
    for (int i = 0; i < 4; i++){
        #pragma unroll
        for (int f = 0; f < 4; f++){
            int row = mb + i*16;
            int col = nb + f*8;
            float v0 = acc[i][f][0], v1 = acc[i][f][1];
            float v2 = acc[i][f][2], v3 = acc[i][f][3];
            if (bias){
                float b0 = __ldg(bias + col), b1 = __ldg(bias + col + 1);
                v0 += b0; v1 += b1; v2 += b0; v3 += b1;
            }
            if (mode == 1){
                v0 = 1.f/(1.f+expf(-v0)); v1 = 1.f/(1.f+expf(-v1));
                v2 = 1.f/(1.f+expf(-v2)); v3 = 1.f/(1.f+expf(-v3));
            } else if (mode == 2){
                v0 = expf(v0); v1 = expf(v1); v2 = expf(v2); v3 = expf(v3);
            }
            float2 o0; o0.x = v0; o0.y = v1;
            float2 o1; o1.x = v2; o1.y = v3;
            *(float2*)(C + (size_t)row * g.N + col)       = o0;
            *(float2*)(C + (size_t)(row + 8) * g.N + col) = o1;
        }
    }
}

// --------------------------- elementwise / prep ------------------------------
__global__ void k_split(const float* __restrict__ in, bf16* __restrict__ h, bf16* __restrict__ l){
    size_t i = (size_t)blockIdx.x * blockDim.x + threadIdx.x;
    float4 v = ((const float4*)in)[i];
    bf16 h0,h1,h2,h3,l0,l1,l2,l3;
    fsplit(v.x,h0,l0); fsplit(v.y,h1,l1); fsplit(v.z,h2,l2); fsplit(v.w,h3,l3);
    ((uint2*)h)[i] = make_uint2(pk2(h0,h1), pk2(h2,h3));
    ((uint2*)l)[i] = make_uint2(pk2(l0,l1), pk2(l2,l3));
}

__global__ void k_ew(const float* __restrict__ wb, __half* __restrict__ h, __half* __restrict__ l){
    size_t i = (size_t)blockIdx.x * blockDim.x + threadIdx.x;
    float4 v = ((const float4*)wb)[i];
    v.x = expf(v.x); v.y = expf(v.y); v.z = expf(v.z); v.w = expf(v.w);
    __half h0,h1,h2,h3,l0,l1,l2,l3;
    fsplit_h(v.x,h0,l0); fsplit_h(v.y,h1,l1); fsplit_h(v.z,h2,l2); fsplit_h(v.w,h3,l3);
    ((uint2*)h)[i] = make_uint2(pk2h(h0,h1), pk2h(h2,h3));
    ((uint2*)l)[i] = make_uint2(pk2h(l0,l1), pk2h(l2,l3));
}

__global__ void k_op(const float* __restrict__ q, const float* __restrict__ num,
                     const float* __restrict__ den, bf16* __restrict__ h, bf16* __restrict__ l){
    size_t i = (size_t)blockIdx.x * blockDim.x + threadIdx.x;
    float4 qv = ((const float4*)q)[i];
    float4 nv = ((const float4*)num)[i];
    float4 dv = ((const float4*)den)[i];
    float4 o;
    o.x = qv.x * nv.x / dv.x; o.y = qv.y * nv.y / dv.y;
    o.z = qv.z * nv.z / dv.z; o.w = qv.w * nv.w / dv.w;
    bf16 h0,h1,h2,h3,l0,l1,l2,l3;
    fsplit(o.x,h0,l0); fsplit(o.y,h1,l1); fsplit(o.z,h2,l2); fsplit(o.w,h3,l3);
    ((uint2*)h)[i] = make_uint2(pk2(h0,h1), pk2(h2,h3));
    ((uint2*)l)[i] = make_uint2(pk2(l0,l1), pk2(l2,l3));
}

// transpose all four weights W_z[DQ,DQ] -> T_z[DQ,DQ] (z = blockIdx.z), split hi/lo
__global__ void k_tsplit4(const float* __restrict__ W0, const float* __restrict__ W1,
                          const float* __restrict__ W2, const float* __restrict__ W3,
                          bf16* __restrict__ Th, bf16* __restrict__ Tl){
    __shared__ float t[32][33];
    int z = blockIdx.z;
    const float* W = (z == 0) ? W0 : (z == 1) ? W1 : (z == 2) ? W2 : W3;
    bf16* th = Th + (size_t)z*DQ*DQ;
    bf16* tl = Tl + (size_t)z*DQ*DQ;
    int x  = blockIdx.x*32 + threadIdx.x;
    int y0 = blockIdx.y*32;
    for (int j = threadIdx.y; j < 32; j += 8)
        t[j][threadIdx.x] = W[(size_t)(y0 + j)*DQ + x];
    __syncthreads();
    int x2  = y0 + threadIdx.x;
    int y20 = blockIdx.x*32;
    for (int j = threadIdx.y; j < 32; j += 8){
        size_t o = (size_t)(y20 + j)*DQ + x2;
        bf16 h, l; fsplit(t[threadIdx.x][j], h, l);
        th[o] = h; tl[o] = l;
    }
}

// per-batch: ekt[d][s]=ek[s][d], ekvt[d][s]=ek[s][d]*v[s][d]  (single fp16)
__global__ void k_prep(const float* __restrict__ ek, const float* __restrict__ v,
                       __half* __restrict__ kt_, __half* __restrict__ kvt){
    __shared__ float t1[32][33], t2[32][33];
    size_t base = (size_t)blockIdx.z * PERB;
    int x  = blockIdx.x*32 + threadIdx.x;   // d
    int y0 = blockIdx.y*32;                 // s base
    for (int j = threadIdx.y; j < 32; j += 8){
        float e  = ek[base + (size_t)(y0 + j)*DQ + x];
        float vv = v [base + (size_t)(y0 + j)*DQ + x];
        t1[j][threadIdx.x] = e;
        t2[j][threadIdx.x] = e * vv;
    }
    __syncthreads();
    int x2  = y0 + threadIdx.x;             // s (out col)
    int y20 = blockIdx.x*32;                // d base (out row)
    for (int j = threadIdx.y; j < 32; j += 8){
        size_t o = base + (size_t)(y20 + j)*TQ + x2;
        kt_[o] = __float2half(t1[threadIdx.x][j]);
        kvt[o] = __float2half(t2[threadIdx.x][j]);
    }
}

// --------------------------------- host -------------------------------------
extern "C" void kernel_launch(void* const* d_in, const int* in_sizes, int n_in,
                              void* d_out, int out_size){
    (void)in_sizes; (void)n_in; (void)out_size;
    const float* x  = (const float*)d_in[0];
    const float* W[4]    = {(const float*)d_in[1], (const float*)d_in[3],
                            (const float*)d_in[5], (const float*)d_in[7]};
    const float* bias[4] = {(const float*)d_in[2], (const float*)d_in[4],
                            (const float*)d_in[6], (const float*)d_in[8]};
    const float* wb = (const float*)d_in[9];
    float* out = (float*)d_out;

    void *ewh,*ewl,*xh,*xl,*wth,*wtl,*qsig,*ek,*v,*ekt,*ekvt,*num,*den,*oph,*opl;
    cudaGetSymbolAddress(&ewh, g_ewh);   cudaGetSymbolAddress(&ewl, g_ewl);
    cudaGetSymbolAddress(&xh, g_xh);     cudaGetSymbolAddress(&xl, g_xl);
    cudaGetSymbolAddress(&wth, g_wth);   cudaGetSymbolAddress(&wtl, g_wtl);
    cudaGetSymbolAddress(&qsig, g_qsig); cudaGetSymbolAddress(&ek, g_ek);
    cudaGetSymbolAddress(&v, g_v);
    cudaGetSymbolAddress(&ekt, g_ekt);   cudaGetSymbolAddress(&ekvt, g_ekvt);
    cudaGetSymbolAddress(&num, g_num);   cudaGetSymbolAddress(&den, g_den);
    cudaGetSymbolAddress(&oph, g_oph);   cudaGetSymbolAddress(&opl, g_opl);

    const int SMEM3 = 3 * 4 * TILE_BYTES;   // 98304
    const int SMEM2 = 4 * 3 * TILE_BYTES;   // 98304
    cudaFuncSetAttribute(gemm_k<3>, cudaFuncAttributeMaxDynamicSharedMemorySize, SMEM3);
    cudaFuncSetAttribute(gemm_k<2>, cudaFuncAttributeMaxDynamicSharedMemorySize, SMEM2);

    dim3 tb(32, 8);
    k_tsplit4<<<dim3(32, 32, 4), tb>>>(W[0], W[1], W[2], W[3], (bf16*)wth, (bf16*)wtl);
    k_split<<<NBTD/1024, 256>>>(x, (bf16*)xh, (bf16*)xl);
    k_ew<<<NTT/1024, 256>>>(wb, (__half*)ewh, (__half*)ewl);

    // projections (one launch, z = q,k,v): C_z = epi_z(X @ W_z + b_z), bf16 3-pass
    {
        GArgs a{};
        a.Ah = xh; a.Al = xl;
        a.M = BTQ; a.N = DQ; a.K = DQ;
        float* Cs[3] = {(float*)qsig, (float*)ek, (float*)v};
        int modes[3] = {1, 2, 0};
        for (int z = 0; z < 3; z++){
            a.B0[z] = (bf16*)wth + (size_t)z*DQ*DQ;
            a.B1[z] = (bf16*)wtl + (size_t)z*DQ*DQ;
            a.C[z] = Cs[z]; a.bias[z] = bias[z]; a.mode[z] = modes[z];
        }
        gemm_k<3><<<dim3(BTQ/128, DQ/128, 3), 256, SMEM3>>>(a);
    }

    k_prep<<<dim3(DQ/32, TQ/32, BQ), tb>>>((float*)ek, (float*)v,
        (__half*)ekt, (__half*)ekvt);

    // mix (one launch, z = 4 batches x {num, den}): ew @ (ekv|ek), fp16 2-pass
    {
        GArgs m{};
        m.Ah = ewh; m.Al = ewl;
        m.M = TQ; m.N = DQ; m.K = TQ;
        for (int z = 0; z < 8; z++){
            int b = z & 3;
            if (z < 4){
                m.B0[z] = (__half*)ekvt + (size_t)b*PERB;
                m.C[z]  = (float*)num + (size_t)b*PERB;
            } else {
                m.B0[z] = (__half*)ekt + (size_t)b*PERB;
                m.C[z]  = (float*)den + (size_t)b*PERB;
            }
            m.B1[z] = nullptr; m.bias[z] = nullptr; m.mode[z] = 0;
        }
        gemm_k<2><<<dim3(TQ/128, DQ/128, 8), 256, SMEM2>>>(m);
    }

    k_op<<<NBTD/1024, 256>>>((float*)qsig, (float*)num, (float*)den,
                             (bf16*)oph, (bf16*)opl);

    // out = OP @ Wo + bo, bf16 3-pass
    {
        GArgs f{};
        f.Ah = oph; f.Al = opl;
        f.B0[0] = (bf16*)wth + (size_t)3*DQ*DQ;
        f.B1[0] = (bf16*)wtl + (size_t)3*DQ*DQ;
        f.C[0] = out; f.bias[0] = bias[3]; f.mode[0] = 0;
        f.M = BTQ; f.N = DQ; f.K = DQ;
        gemm_k<3><<<dim3(BTQ/128, DQ/128, 1), 256, SMEM3>>>(f);
    }
}

// round 7
// speedup vs baseline: 2.0534x; 1.1825x over previous
#include <cuda_runtime.h>
#include <cuda_bf16.h>
#include <cuda_fp16.h>
#include <cstdint>
#include <math.h>

#define BQ 4
#define TQ 2048
#define DQ 1024
#define BTQ 8192                 // B*T
#define NTT (TQ*TQ)              // 4194304
#define NBTD (BTQ*DQ)            // 8388608
#define PERB (TQ*DQ)             // 2097152

// ------------------------- scratch (device globals) -------------------------
__device__ __half g_ewh[NTT],  g_ewl[NTT];            // fp16 hi/lo of exp(wbias)
__device__ __half g_xh[NBTD],  g_xl[NBTD];            // fp16 hi/lo of x
__device__ __half g_wt[4][DQ*DQ];                     // transposed weights, single fp16
__device__ float  g_qsig[NBTD], g_ek[NBTD], g_v[NBTD];
__device__ __half g_ekt[NBTD], g_ekvt[NBTD];          // fp16 single (B of mix)
__device__ float  g_num[NBTD], g_den[NBTD];
__device__ __half g_oph[NBTD], g_opl[NBTD];           // fp16 hi/lo of op

// ------------------------------- helpers ------------------------------------
__device__ __forceinline__ uint32_t smem_u32(const void* p){
    uint32_t a;
    asm("{ .reg .u64 t; cvta.to.shared.u64 t, %1; cvt.u32.u64 %0, t; }" : "=r"(a) : "l"(p));
    return a;
}
__device__ __forceinline__ void ldsm4(uint32_t* r, uint32_t addr){
    asm volatile("ldmatrix.sync.aligned.m8n8.x4.shared.b16 {%0,%1,%2,%3}, [%4];"
        : "=r"(r[0]),"=r"(r[1]),"=r"(r[2]),"=r"(r[3]) : "r"(addr));
}
__device__ __forceinline__ void mma_f16(float* d, const uint32_t* a, const uint32_t* b){
    asm volatile("mma.sync.aligned.m16n8k16.row.col.f32.f16.f16.f32 "
        "{%0,%1,%2,%3}, {%4,%5,%6,%7}, {%8,%9}, {%0,%1,%2,%3};"
        : "+f"(d[0]),"+f"(d[1]),"+f"(d[2]),"+f"(d[3])
        : "r"(a[0]),"r"(a[1]),"r"(a[2]),"r"(a[3]), "r"(b[0]),"r"(b[1]));
}
__device__ __forceinline__ void cp16(uint32_t saddr, const void* g){
    asm volatile("cp.async.cg.shared.global [%0], [%1], 16;" :: "r"(saddr), "l"(g));
}
__device__ __forceinline__ void fsplit_h(float f, __half& h, __half& l){
    h = __float2half(f);
    l = __float2half(f - __half2float(h));
}
__device__ __forceinline__ uint32_t pk2h(__half a, __half b){
    return (uint32_t)__half_as_ushort(a) | ((uint32_t)__half_as_ushort(b) << 16);
}

// 128-row x 32-elem (64B) tile, XOR-swizzled: 16B-aligned, LDSM conflict-free
#define TILE_BYTES 8192
__device__ __forceinline__ uint32_t swz(uint32_t row, uint32_t chunk){
    return row*64u + (((chunk ^ (row >> 1)) & 3u) << 4);
}

// --------------------------------- GEMM -------------------------------------
// fp16 A-split 2-pass: C = (Ah+Al) @ B^T, B single fp16, f32 acc.
// A:[M,K] row-major, B:[N,K] row-major. BM=BN=128, BK=32, 256 thr, 4 stages.
#define MAXZ 8
struct GArgs {
    const void *Ah, *Al;
    const void *B0[MAXZ];
    float* C[MAXZ];
    const float* bias[MAXZ];           // may be null
    int mode[MAXZ];                    // 0 none, 1 sigmoid, 2 exp
    int M, N, K;
};

#define NT    3                        // tiles per stage (Ah, Al, B)
#define NST   4                        // stages
#define PF    3                        // prefetch distance
#define STAGE (NT * TILE_BYTES)        // 24576
#define GEMM_SMEM (NST * STAGE)        // 98304

__global__ void __launch_bounds__(256, 2)
gemm_k(GArgs g){
    extern __shared__ char smem[];
    uint32_t sb = smem_u32(smem);
    int tid = threadIdx.x, wid = tid >> 5, lane = tid & 31;
    int wm = wid & 1, wn = wid >> 1;                  // 2 x 4 warp grid
    int z = blockIdx.z;

    const char* bases[3];
    bases[0] = (const char*)g.Ah;
    bases[1] = (const char*)g.Al;
    bases[2] = (const char*)g.B0[z];
    float* C = g.C[z];
    const float* bias = g.bias[z];
    int mode = g.mode[z];
    int m0 = blockIdx.x * 128, n0 = blockIdx.y * 128;
    const size_t ldk = (size_t)g.K;
    const int KT = g.K >> 5;
    int ro[3] = {m0, m0, n0};

    float acc[4][4][4];
    #pragma unroll
    for (int i = 0; i < 4; i++)
        #pragma unroll
        for (int f = 0; f < 4; f++)
            #pragma unroll
            for (int r = 0; r < 4; r++) acc[i][f][r] = 0.f;

    auto issue = [&](int kt, int stage){
        uint32_t sbase = sb + stage*STAGE;
        #pragma unroll
        for (int t = 0; t < NT; t++){
            #pragma unroll
            for (int hh = 0; hh < 2; hh++){
                int c = (hh << 8) + tid;              // 0..511 within tile
                uint32_t row = (uint32_t)(c >> 2), ch = (uint32_t)(c & 3);
                uint32_t saddr = sbase + t*TILE_BYTES + swz(row, ch);
                const char* gp = bases[t]
                    + (((size_t)ro[t] + row)*ldk + (size_t)kt*32 + ch*8)*2;
                cp16(saddr, gp);
            }
        }
        asm volatile("cp.async.commit_group;" ::: "memory");
    };

    #pragma unroll
    for (int s = 0; s < PF; s++) issue(s, s);

    // ldmatrix lane addressing (fixed per thread)
    uint32_t a_row = wm*64 + (lane & 15);
    uint32_t a_ch0 = (lane >> 4) & 1;
    uint32_t b_row = wn*32 + ((lane >> 4) & 1)*8 + (lane & 7);
    uint32_t b_ch0 = (lane >> 3) & 1;

    for (int kt = 0; kt < KT; kt++){
        int ahead = KT - 1 - kt; if (ahead > PF - 1) ahead = PF - 1;
        if (ahead == 2)      asm volatile("cp.async.wait_group 2;" ::: "memory");
        else if (ahead == 1) asm volatile("cp.async.wait_group 1;" ::: "memory");
        else                 asm volatile("cp.async.wait_group 0;" ::: "memory");
        __syncthreads();
        if (kt + PF < KT) issue(kt + PF, (kt + PF) % NST);

        uint32_t st = sb + (kt % NST)*STAGE;
        #pragma unroll
        for (uint32_t j = 0; j < 2; j++){
            uint32_t ca = j*2 + a_ch0;
            uint32_t cb = j*2 + b_ch0;
            uint32_t a[4][4], b[2][4];

            // pass 0: Ah x B
            #pragma unroll
            for (uint32_t i = 0; i < 4; i++)
                ldsm4(a[i], st + swz(a_row + i*16, ca));
            #pragma unroll
            for (uint32_t q = 0; q < 2; q++)
                ldsm4(b[q], st + 2*TILE_BYTES + swz(b_row + q*16, cb));
            #pragma unroll
            for (int i = 0; i < 4; i++)
                #pragma unroll
                for (int f = 0; f < 4; f++)
                    mma_f16(acc[i][f], a[i], &b[f>>1][(f&1)*2]);

            // pass 1: Al x B (b kept live)
            #pragma unroll
            for (uint32_t i = 0; i < 4; i++)
                ldsm4(a[i], st + TILE_BYTES + swz(a_row + i*16, ca));
            #pragma unroll
            for (int i = 0; i < 4; i++)
                #pragma unroll
                for (int f = 0; f < 4; f++)
                    mma_f16(acc[i][f], a[i], &b[f>>1][(f&1)*2]);
        }
    }

    // ------------------------------ epilogue --------------------------------
    int mb = m0 + wm*64 + (lane >> 2);
    int nb = n0 + wn*32 + (lane & 3)*2;
    #pragma unroll
    for (int i = 0; i < 4; i++){
        #pragma unroll
        for (int f = 0; f < 4; f++){
            int row = mb + i*16;
            int col = nb + f*8;
            float v0 = acc[i][f][0], v1 = acc[i][f][1];
            float v2 = acc[i][f][2], v3 = acc[i][f][3];
            if (bias){
                float b0 = __ldg(bias + col), b1 = __ldg(bias + col + 1);
                v0 += b0; v1 += b1; v2 += b0; v3 += b1;
            }
            if (mode == 1){
                v0 = 1.f/(1.f+expf(-v0)); v1 = 1.f/(1.f+expf(-v1));
                v2 = 1.f/(1.f+expf(-v2)); v3 = 1.f/(1.f+expf(-v3));
            } else if (mode == 2){
                v0 = expf(v0); v1 = expf(v1); v2 = expf(v2); v3 = expf(v3);
            }
            float2 o0; o0.x = v0; o0.y = v1;
            float2 o1; o1.x = v2; o1.y = v3;
            *(float2*)(C + (size_t)row * g.N + col)       = o0;
            *(float2*)(C + (size_t)(row + 8) * g.N + col) = o1;
        }
    }
}

// --------------------------- elementwise / prep ------------------------------
__global__ void k_splith(const float* __restrict__ in, __half* __restrict__ h,
                         __half* __restrict__ l){
    size_t i = (size_t)blockIdx.x * blockDim.x + threadIdx.x;
    float4 v = ((const float4*)in)[i];
    __half h0,h1,h2,h3,l0,l1,l2,l3;
    fsplit_h(v.x,h0,l0); fsplit_h(v.y,h1,l1); fsplit_h(v.z,h2,l2); fsplit_h(v.w,h3,l3);
    ((uint2*)h)[i] = make_uint2(pk2h(h0,h1), pk2h(h2,h3));
    ((uint2*)l)[i] = make_uint2(pk2h(l0,l1), pk2h(l2,l3));
}

__global__ void k_ew(const float* __restrict__ wb, __half* __restrict__ h, __half* __restrict__ l){
    size_t i = (size_t)blockIdx.x * blockDim.x + threadIdx.x;
    float4 v = ((const float4*)wb)[i];
    v.x = expf(v.x); v.y = expf(v.y); v.z = expf(v.z); v.w = expf(v.w);
    __half h0,h1,h2,h3,l0,l1,l2,l3;
    fsplit_h(v.x,h0,l0); fsplit_h(v.y,h1,l1); fsplit_h(v.z,h2,l2); fsplit_h(v.w,h3,l3);
    ((uint2*)h)[i] = make_uint2(pk2h(h0,h1), pk2h(h2,h3));
    ((uint2*)l)[i] = make_uint2(pk2h(l0,l1), pk2h(l2,l3));
}

__global__ void k_op(const float* __restrict__ q, const float* __restrict__ num,
                     const float* __restrict__ den, __half* __restrict__ h,
                     __half* __restrict__ l){
    size_t i = (size_t)blockIdx.x * blockDim.x + threadIdx.x;
    float4 qv = ((const float4*)q)[i];
    float4 nv = ((const float4*)num)[i];
    float4 dv = ((const float4*)den)[i];
    float4 o;
    o.x = qv.x * nv.x / dv.x; o.y = qv.y * nv.y / dv.y;
    o.z = qv.z * nv.z / dv.z; o.w = qv.w * nv.w / dv.w;
    __half h0,h1,h2,h3,l0,l1,l2,l3;
    fsplit_h(o.x,h0,l0); fsplit_h(o.y,h1,l1); fsplit_h(o.z,h2,l2); fsplit_h(o.w,h3,l3);
    ((uint2*)h)[i] = make_uint2(pk2h(h0,h1), pk2h(h2,h3));
    ((uint2*)l)[i] = make_uint2(pk2h(l0,l1), pk2h(l2,l3));
}

// transpose all four weights W_z[DQ,DQ] -> T_z[DQ,DQ] (z = blockIdx.z), single fp16
__global__ void k_tsplit4(const float* __restrict__ W0, const float* __restrict__ W1,
                          const float* __restrict__ W2, const float* __restrict__ W3,
                          __half* __restrict__ Tw){
    __shared__ float t[32][33];
    int z = blockIdx.z;
    const float* W = (z == 0) ? W0 : (z == 1) ? W1 : (z == 2) ? W2 : W3;
    __half* tw = Tw + (size_t)z*DQ*DQ;
    int x  = blockIdx.x*32 + threadIdx.x;
    int y0 = blockIdx.y*32;
    for (int j = threadIdx.y; j < 32; j += 8)
        t[j][threadIdx.x] = W[(size_t)(y0 + j)*DQ + x];
    __syncthreads();
    int x2  = y0 + threadIdx.x;
    int y20 = blockIdx.x*32;
    for (int j = threadIdx.y; j < 32; j += 8){
        size_t o = (size_t)(y20 + j)*DQ + x2;
        tw[o] = __float2half(t[threadIdx.x][j]);
    }
}

// per-batch: ekt[d][s]=ek[s][d], ekvt[d][s]=ek[s][d]*v[s][d]  (single fp16)
__global__ void k_prep(const float* __restrict__ ek, const float* __restrict__ v,
                       __half* __restrict__ kt_, __half* __restrict__ kvt){
    __shared__ float t1[32][33], t2[32][33];
    size_t base = (size_t)blockIdx.z * PERB;
    int x  = blockIdx.x*32 + threadIdx.x;   // d
    int y0 = blockIdx.y*32;                 // s base
    for (int j = threadIdx.y; j < 32; j += 8){
        float e  = ek[base + (size_t)(y0 + j)*DQ + x];
        float vv = v [base + (size_t)(y0 + j)*DQ + x];
        t1[j][threadIdx.x] = e;
        t2[j][threadIdx.x] = e * vv;
    }
    __syncthreads();
    int x2  = y0 + threadIdx.x;             // s (out col)
    int y20 = blockIdx.x*32;                // d base (out row)
    for (int j = threadIdx.y; j < 32; j += 8){
        size_t o = base + (size_t)(y20 + j)*TQ + x2;
        kt_[o] = __float2half(t1[threadIdx.x][j]);
        kvt[o] = __float2half(t2[threadIdx.x][j]);
    }
}

// --------------------------------- host -------------------------------------
extern "C" void kernel_launch(void* const* d_in, const int* in_sizes, int n_in,
                              void* d_out, int out_size){
    (void)in_sizes; (void)n_in; (void)out_size;
    const float* x  = (const float*)d_in[0];
    const float* W[4]    = {(const float*)d_in[1], (const float*)d_in[3],
                            (const float*)d_in[5], (const float*)d_in[7]};
    const float* bias[4] = {(const float*)d_in[2], (const float*)d_in[4],
                            (const float*)d_in[6], (const float*)d_in[8]};
    const float* wb = (const float*)d_in[9];
    float* out = (float*)d_out;

    void *ewh,*ewl,*xh,*xl,*wt,*qsig,*ek,*v,*ekt,*ekvt,*num,*den,*oph,*opl;
    cudaGetSymbolAddress(&ewh, g_ewh);   cudaGetSymbolAddress(&ewl, g_ewl);
    cudaGetSymbolAddress(&xh, g_xh);     cudaGetSymbolAddress(&xl, g_xl);
    cudaGetSymbolAddress(&wt, g_wt);
    cudaGetSymbolAddress(&qsig, g_qsig); cudaGetSymbolAddress(&ek, g_ek);
    cudaGetSymbolAddress(&v, g_v);
    cudaGetSymbolAddress(&ekt, g_ekt);   cudaGetSymbolAddress(&ekvt, g_ekvt);
    cudaGetSymbolAddress(&num, g_num);   cudaGetSymbolAddress(&den, g_den);
    cudaGetSymbolAddress(&oph, g_oph);   cudaGetSymbolAddress(&opl, g_opl);

    cudaFuncSetAttribute(gemm_k, cudaFuncAttributeMaxDynamicSharedMemorySize, GEMM_SMEM);

    dim3 tb(32, 8);
    k_tsplit4<<<dim3(32, 32, 4), tb>>>(W[0], W[1], W[2], W[3], (__half*)wt);
    k_splith<<<NBTD/1024, 256>>>(x, (__half*)xh, (__half*)xl);
    k_ew<<<NTT/1024, 256>>>(wb, (__half*)ewh, (__half*)ewl);

    // projections (one launch, z = q,k,v): C_z = epi_z(X @ W_z + b_z)
    {
        GArgs a{};
        a.Ah = xh; a.Al = xl;
        a.M = BTQ; a.N = DQ; a.K = DQ;
        float* Cs[3] = {(float*)qsig, (float*)ek, (float*)v};
        int modes[3] = {1, 2, 0};
        for (int z = 0; z < 3; z++){
            a.B0[z] = (__half*)wt + (size_t)z*DQ*DQ;
            a.C[z] = Cs[z]; a.bias[z] = bias[z]; a.mode[z] = modes[z];
        }
        gemm_k<<<dim3(BTQ/128, DQ/128, 3), 256, GEMM_SMEM>>>(a);
    }

    k_prep<<<dim3(DQ/32, TQ/32, BQ), tb>>>((float*)ek, (float*)v,
        (__half*)ekt, (__half*)ekvt);

    // mix (one launch, z = 4 batches x {num, den}): ew @ (ekv|ek)
    {
        GArgs m{};
        m.Ah = ewh; m.Al = ewl;
        m.M = TQ; m.N = DQ; m.K = TQ;
        for (int z = 0; z < 8; z++){
            int b = z & 3;
            if (z < 4){
                m.B0[z] = (__half*)ekvt + (size_t)b*PERB;
                m.C[z]  = (float*)num + (size_t)b*PERB;
            } else {
                m.B0[z] = (__half*)ekt + (size_t)b*PERB;
                m.C[z]  = (float*)den + (size_t)b*PERB;
            }
            m.bias[z] = nullptr; m.mode[z] = 0;
        }
        gemm_k<<<dim3(TQ/128, DQ/128, 8), 256, GEMM_SMEM>>>(m);
    }

    k_op<<<NBTD/1024, 256>>>((float*)qsig, (float*)num, (float*)den,
                             (__half*)oph, (__half*)opl);

    // out = OP @ Wo + bo
    {
        GArgs f{};
        f.Ah = oph; f.Al = opl;
        f.B0[0] = (__half*)wt + (size_t)3*DQ*DQ;
        f.C[0] = out; f.bias[0] = bias[3]; f.mode[0] = 0;
        f.M = BTQ; f.N = DQ; f.K = DQ;
        gemm_k<<<dim3(BTQ/128, DQ/128, 1), 256, GEMM_SMEM>>>(f);
    }
}

// round 8
// speedup vs baseline: 2.1568x; 1.0503x over previous
#include <cuda_runtime.h>
#include <cuda_bf16.h>
#include <cuda_fp16.h>
#include <cstdint>
#include <math.h>

#define BQ 4
#define TQ 2048
#define DQ 1024
#define BTQ 8192                 // B*T
#define NTT (TQ*TQ)              // 4194304
#define NBTD (BTQ*DQ)            // 8388608
#define PERB (TQ*DQ)             // 2097152

// ------------------------- scratch (device globals) -------------------------
__device__ __half g_ewh[NTT],  g_ewl[NTT];            // fp16 hi/lo of exp(wbias)
__device__ __half g_xh[NBTD],  g_xl[NBTD];            // fp16 hi/lo of x
__device__ __half g_wt[4][DQ*DQ];                     // transposed weights, single fp16
__device__ float  g_qsig[NBTD], g_ek[NBTD], g_v[NBTD];
__device__ __half g_ekt[NBTD], g_ekvt[NBTD];          // fp16 single (B of mix)
__device__ float  g_num[NBTD], g_den[NBTD];
__device__ __half g_oph[NBTD], g_opl[NBTD];           // fp16 hi/lo of op

// ------------------------------- helpers ------------------------------------
__device__ __forceinline__ uint32_t smem_u32(const void* p){
    uint32_t a;
    asm("{ .reg .u64 t; cvta.to.shared.u64 t, %1; cvt.u32.u64 %0, t; }" : "=r"(a) : "l"(p));
    return a;
}
__device__ __forceinline__ void ldsm4(uint32_t* r, uint32_t addr){
    asm volatile("ldmatrix.sync.aligned.m8n8.x4.shared.b16 {%0,%1,%2,%3}, [%4];"
        : "=r"(r[0]),"=r"(r[1]),"=r"(r[2]),"=r"(r[3]) : "r"(addr));
}
__device__ __forceinline__ void mma_f16(float* d, const uint32_t* a, const uint32_t* b){
    asm volatile("mma.sync.aligned.m16n8k16.row.col.f32.f16.f16.f32 "
        "{%0,%1,%2,%3}, {%4,%5,%6,%7}, {%8,%9}, {%0,%1,%2,%3};"
        : "+f"(d[0]),"+f"(d[1]),"+f"(d[2]),"+f"(d[3])
        : "r"(a[0]),"r"(a[1]),"r"(a[2]),"r"(a[3]), "r"(b[0]),"r"(b[1]));
}
__device__ __forceinline__ void cp16(uint32_t saddr, const void* g){
    asm volatile("cp.async.cg.shared.global [%0], [%1], 16;" :: "r"(saddr), "l"(g));
}
__device__ __forceinline__ void fsplit_h(float f, __half& h, __half& l){
    h = __float2half(f);
    l = __float2half(f - __half2float(h));
}
__device__ __forceinline__ uint32_t pk2h(__half a, __half b){
    return (uint32_t)__half_as_ushort(a) | ((uint32_t)__half_as_ushort(b) << 16);
}

// 128-row x 32-elem (64B) tile, XOR-swizzled: 16B-aligned, LDSM conflict-free
#define TILE_BYTES 8192
__device__ __forceinline__ uint32_t swz(uint32_t row, uint32_t chunk){
    return row*64u + (((chunk ^ (row >> 1)) & 3u) << 4);
}

// --------------------------------- GEMM -------------------------------------
// fp16 A-split 2-pass: C = (Ah+Al) @ B^T, B single fp16, f32 acc.
// A:[M,K] row-major, B:[N,K] row-major. BM=BN=128, BK=32, 256 thr, 4 stages,
// paired k-tiles: ONE barrier per two k-tiles.
#define MAXZ 8
struct GArgs {
    const void *Ah, *Al;
    const void *B0[MAXZ];
    float* C[MAXZ];
    const float* bias[MAXZ];           // may be null
    int mode[MAXZ];                    // 0 none, 1 sigmoid, 2 exp
    int M, N, K;
};

#define NT    3                        // tiles per stage (Ah, Al, B)
#define NST   4                        // stages
#define STAGE (NT * TILE_BYTES)        // 24576
#define GEMM_SMEM (NST * STAGE)        // 98304

__global__ void __launch_bounds__(256, 2)
gemm_k(GArgs g){
    extern __shared__ char smem[];
    uint32_t sb = smem_u32(smem);
    int tid = threadIdx.x, wid = tid >> 5, lane = tid & 31;
    int wm = wid & 1, wn = wid >> 1;                  // 2 x 4 warp grid
    int z = blockIdx.z;

    const char* bases[3];
    bases[0] = (const char*)g.Ah;
    bases[1] = (const char*)g.Al;
    bases[2] = (const char*)g.B0[z];
    float* C = g.C[z];
    const float* bias = g.bias[z];
    int mode = g.mode[z];
    int m0 = blockIdx.x * 128, n0 = blockIdx.y * 128;
    const size_t ldk = (size_t)g.K;
    const int KT = g.K >> 5;                          // even for all our K
    int ro[3] = {m0, m0, n0};

    float acc[4][4][4];
    #pragma unroll
    for (int i = 0; i < 4; i++)
        #pragma unroll
        for (int f = 0; f < 4; f++)
            #pragma unroll
            for (int r = 0; r < 4; r++) acc[i][f][r] = 0.f;

    auto issue = [&](int kt, int stage){
        uint32_t sbase = sb + stage*STAGE;
        #pragma unroll
        for (int t = 0; t < NT; t++){
            #pragma unroll
            for (int hh = 0; hh < 2; hh++){
                int c = (hh << 8) + tid;              // 0..511 within tile
                uint32_t row = (uint32_t)(c >> 2), ch = (uint32_t)(c & 3);
                uint32_t saddr = sbase + t*TILE_BYTES + swz(row, ch);
                const char* gp = bases[t]
                    + (((size_t)ro[t] + row)*ldk + (size_t)kt*32 + ch*8)*2;
                cp16(saddr, gp);
            }
        }
        asm volatile("cp.async.commit_group;" ::: "memory");
    };

    // ldmatrix lane addressing (fixed per thread)
    uint32_t a_row = wm*64 + (lane & 15);
    uint32_t a_ch0 = (lane >> 4) & 1;
    uint32_t b_row = wn*32 + ((lane >> 4) & 1)*8 + (lane & 7);
    uint32_t b_ch0 = (lane >> 3) & 1;

    auto compute = [&](int kt){
        uint32_t st = sb + (kt & 3)*STAGE;
        #pragma unroll
        for (uint32_t j = 0; j < 2; j++){
            uint32_t ca = j*2 + a_ch0;
            uint32_t cb = j*2 + b_ch0;
            uint32_t a[4][4], b[2][4];

            // pass 0: Ah x B
            #pragma unroll
            for (uint32_t i = 0; i < 4; i++)
                ldsm4(a[i], st + swz(a_row + i*16, ca));
            #pragma unroll
            for (uint32_t q = 0; q < 2; q++)
                ldsm4(b[q], st + 2*TILE_BYTES + swz(b_row + q*16, cb));
            #pragma unroll
            for (int i = 0; i < 4; i++)
                #pragma unroll
                for (int f = 0; f < 4; f++)
                    mma_f16(acc[i][f], a[i], &b[f>>1][(f&1)*2]);

            // pass 1: Al x B (b kept live)
            #pragma unroll
            for (uint32_t i = 0; i < 4; i++)
                ldsm4(a[i], st + TILE_BYTES + swz(a_row + i*16, ca));
            #pragma unroll
            for (int i = 0; i < 4; i++)
                #pragma unroll
                for (int f = 0; f < 4; f++)
                    mma_f16(acc[i][f], a[i], &b[f>>1][(f&1)*2]);
        }
    };

    issue(0, 0);
    issue(1, 1);

    for (int kt = 0; kt < KT; kt += 2){
        asm volatile("cp.async.wait_group 0;" ::: "memory");
        __syncthreads();
        if (kt + 2 < KT){
            issue(kt + 2, (kt + 2) & 3);
            issue(kt + 3, (kt + 3) & 3);
        }
        compute(kt);
        compute(kt + 1);
    }

    // ------------------------------ epilogue --------------------------------
    int mb = m0 + wm*64 + (lane >> 2);
    int nb = n0 + wn*32 + (lane & 3)*2;
    #pragma unroll
    for (int i = 0; i < 4; i++){
        #pragma unroll
        for (int f = 0; f < 4; f++){
            int row = mb + i*16;
            int col = nb + f*8;
            float v0 = acc[i][f][0], v1 = acc[i][f][1];
            float v2 = acc[i][f][2], v3 = acc[i][f][3];
            if (bias){
                float b0 = __ldg(bias + col), b1 = __ldg(bias + col + 1);
                v0 += b0; v1 += b1; v2 += b0; v3 += b1;
            }
            if (mode == 1){
                v0 = 1.f/(1.f+expf(-v0)); v1 = 1.f/(1.f+expf(-v1));
                v2 = 1.f/(1.f+expf(-v2)); v3 = 1.f/(1.f+expf(-v3));
            } else if (mode == 2){
                v0 = expf(v0); v1 = expf(v1); v2 = expf(v2); v3 = expf(v3);
            }
            float2 o0; o0.x = v0; o0.y = v1;
            float2 o1; o1.x = v2; o1.y = v3;
            *(float2*)(C + (size_t)row * g.N + col)       = o0;
            *(float2*)(C + (size_t)(row + 8) * g.N + col) = o1;
        }
    }
}

// --------------------------- elementwise / prep ------------------------------
__global__ void k_splith(const float* __restrict__ in, __half* __restrict__ h,
                         __half* __restrict__ l){
    size_t i = (size_t)blockIdx.x * blockDim.x + threadIdx.x;
    float4 v = ((const float4*)in)[i];
    __half h0,h1,h2,h3,l0,l1,l2,l3;
    fsplit_h(v.x,h0,l0); fsplit_h(v.y,h1,l1); fsplit_h(v.z,h2,l2); fsplit_h(v.w,h3,l3);
    ((uint2*)h)[i] = make_uint2(pk2h(h0,h1), pk2h(h2,h3));
    ((uint2*)l)[i] = make_uint2(pk2h(l0,l1), pk2h(l2,l3));
}

__global__ void k_ew(const float* __restrict__ wb, __half* __restrict__ h, __half* __restrict__ l){
    size_t i = (size_t)blockIdx.x * blockDim.x + threadIdx.x;
    float4 v = ((const float4*)wb)[i];
    v.x = expf(v.x); v.y = expf(v.y); v.z = expf(v.z); v.w = expf(v.w);
    __half h0,h1,h2,h3,l0,l1,l2,l3;
    fsplit_h(v.x,h0,l0); fsplit_h(v.y,h1,l1); fsplit_h(v.z,h2,l2); fsplit_h(v.w,h3,l3);
    ((uint2*)h)[i] = make_uint2(pk2h(h0,h1), pk2h(h2,h3));
    ((uint2*)l)[i] = make_uint2(pk2h(l0,l1), pk2h(l2,l3));
}

__global__ void k_op(const float* __restrict__ q, const float* __restrict__ num,
                     const float* __restrict__ den, __half* __restrict__ h,
                     __half* __restrict__ l){
    size_t i = (size_t)blockIdx.x * blockDim.x + threadIdx.x;
    float4 qv = ((const float4*)q)[i];
    float4 nv = ((const float4*)num)[i];
    float4 dv = ((const float4*)den)[i];
    float4 o;
    o.x = qv.x * nv.x / dv.x; o.y = qv.y * nv.y / dv.y;
    o.z = qv.z * nv.z / dv.z; o.w = qv.w * nv.w / dv.w;
    __half h0,h1,h2,h3,l0,l1,l2,l3;
    fsplit_h(o.x,h0,l0); fsplit_h(o.y,h1,l1); fsplit_h(o.z,h2,l2); fsplit_h(o.w,h3,l3);
    ((uint2*)h)[i] = make_uint2(pk2h(h0,h1), pk2h(h2,h3));
    ((uint2*)l)[i] = make_uint2(pk2h(l0,l1), pk2h(l2,l3));
}

// transpose all four weights W_z[DQ,DQ] -> T_z[DQ,DQ] (z = blockIdx.z), single fp16
__global__ void k_tsplit4(const float* __restrict__ W0, const float* __restrict__ W1,
                          const float* __restrict__ W2, const float* __restrict__ W3,
                          __half* __restrict__ Tw){
    __shared__ float t[32][33];
    int z = blockIdx.z;
    const float* W = (z == 0) ? W0 : (z == 1) ? W1 : (z == 2) ? W2 : W3;
    __half* tw = Tw + (size_t)z*DQ*DQ;
    int x  = blockIdx.x*32 + threadIdx.x;
    int y0 = blockIdx.y*32;
    for (int j = threadIdx.y; j < 32; j += 8)
        t[j][threadIdx.x] = W[(size_t)(y0 + j)*DQ + x];
    __syncthreads();
    int x2  = y0 + threadIdx.x;
    int y20 = blockIdx.x*32;
    for (int j = threadIdx.y; j < 32; j += 8){
        size_t o = (size_t)(y20 + j)*DQ + x2;
        tw[o] = __float2half(t[threadIdx.x][j]);
    }
}

// per-batch: ekt[d][s]=ek[s][d], ekvt[d][s]=ek[s][d]*v[s][d]  (single fp16)
__global__ void k_prep(const float* __restrict__ ek, const float* __restrict__ v,
                       __half* __restrict__ kt_, __half* __restrict__ kvt){
    __shared__ float t1[32][33], t2[32][33];
    size_t base = (size_t)blockIdx.z * PERB;
    int x  = blockIdx.x*32 + threadIdx.x;   // d
    int y0 = blockIdx.y*32;                 // s base
    for (int j = threadIdx.y; j < 32; j += 8){
        float e  = ek[base + (size_t)(y0 + j)*DQ + x];
        float vv = v [base + (size_t)(y0 + j)*DQ + x];
        t1[j][threadIdx.x] = e;
        t2[j][threadIdx.x] = e * vv;
    }
    __syncthreads();
    int x2  = y0 + threadIdx.x;             // s (out col)
    int y20 = blockIdx.x*32;                // d base (out row)
    for (int j = threadIdx.y; j < 32; j += 8){
        size_t o = base + (size_t)(y20 + j)*TQ + x2;
        kt_[o] = __float2half(t1[threadIdx.x][j]);
        kvt[o] = __float2half(t2[threadIdx.x][j]);
    }
}

// --------------------------------- host -------------------------------------
extern "C" void kernel_launch(void* const* d_in, const int* in_sizes, int n_in,
                              void* d_out, int out_size){
    (void)in_sizes; (void)n_in; (void)out_size;
    const float* x  = (const float*)d_in[0];
    const float* W[4]    = {(const float*)d_in[1], (const float*)d_in[3],
                            (const float*)d_in[5], (const float*)d_in[7]};
    const float* bias[4] = {(const float*)d_in[2], (const float*)d_in[4],
                            (const float*)d_in[6], (const float*)d_in[8]};
    const float* wb = (const float*)d_in[9];
    float* out = (float*)d_out;

    void *ewh,*ewl,*xh,*xl,*wt,*qsig,*ek,*v,*ekt,*ekvt,*num,*den,*oph,*opl;
    cudaGetSymbolAddress(&ewh, g_ewh);   cudaGetSymbolAddress(&ewl, g_ewl);
    cudaGetSymbolAddress(&xh, g_xh);     cudaGetSymbolAddress(&xl, g_xl);
    cudaGetSymbolAddress(&wt, g_wt);
    cudaGetSymbolAddress(&qsig, g_qsig); cudaGetSymbolAddress(&ek, g_ek);
    cudaGetSymbolAddress(&v, g_v);
    cudaGetSymbolAddress(&ekt, g_ekt);   cudaGetSymbolAddress(&ekvt, g_ekvt);
    cudaGetSymbolAddress(&num, g_num);   cudaGetSymbolAddress(&den, g_den);
    cudaGetSymbolAddress(&oph, g_oph);   cudaGetSymbolAddress(&opl, g_opl);

    cudaFuncSetAttribute(gemm_k, cudaFuncAttributeMaxDynamicSharedMemorySize, GEMM_SMEM);

    dim3 tb(32, 8);
    k_tsplit4<<<dim3(32, 32, 4), tb>>>(W[0], W[1], W[2], W[3], (__half*)wt);
    k_splith<<<NBTD/1024, 256>>>(x, (__half*)xh, (__half*)xl);
    k_ew<<<NTT/1024, 256>>>(wb, (__half*)ewh, (__half*)ewl);

    // projections (one launch, z = q,k,v): C_z = epi_z(X @ W_z + b_z)
    {
        GArgs a{};
        a.Ah = xh; a.Al = xl;
        a.M = BTQ; a.N = DQ; a.K = DQ;
        float* Cs[3] = {(float*)qsig, (float*)ek, (float*)v};
        int modes[3] = {1, 2, 0};
        for (int z = 0; z < 3; z++){
            a.B0[z] = (__half*)wt + (size_t)z*DQ*DQ;
            a.C[z] = Cs[z]; a.bias[z] = bias[z]; a.mode[z] = modes[z];
        }
        gemm_k<<<dim3(BTQ/128, DQ/128, 3), 256, GEMM_SMEM>>>(a);
    }

    k_prep<<<dim3(DQ/32, TQ/32, BQ), tb>>>((float*)ek, (float*)v,
        (__half*)ekt, (__half*)ekvt);

    // mix (one launch, z = 4 batches x {num, den}): ew @ (ekv|ek)
    {
        GArgs m{};
        m.Ah = ewh; m.Al = ewl;
        m.M = TQ; m.N = DQ; m.K = TQ;
        for (int z = 0; z < 8; z++){
            int b = z & 3;
            if (z < 4){
                m.B0[z] = (__half*)ekvt + (size_t)b*PERB;
                m.C[z]  = (float*)num + (size_t)b*PERB;
            } else {
                m.B0[z] = (__half*)ekt + (size_t)b*PERB;
                m.C[z]  = (float*)den + (size_t)b*PERB;
            }
            m.bias[z] = nullptr; m.mode[z] = 0;
        }
        gemm_k<<<dim3(TQ/128, DQ/128, 8), 256, GEMM_SMEM>>>(m);
    }

    k_op<<<NBTD/1024, 256>>>((float*)qsig, (float*)num, (float*)den,
                             (__half*)oph, (__half*)opl);

    // out = OP @ Wo + bo
    {
        GArgs f{};
        f.Ah = oph; f.Al = opl;
        f.B0[0] = (__half*)wt + (size_t)3*DQ*DQ;
        f.C[0] = out; f.bias[0] = bias[3]; f.mode[0] = 0;
        f.M = BTQ; f.N = DQ; f.K = DQ;
        gemm_k<<<dim3(BTQ/128, DQ/128, 1), 256, GEMM_SMEM>>>(f);
    }
}